// round 12
// baseline (speedup 1.0000x reference)
#include <cuda_runtime.h>
#include <cuda_fp16.h>
#include <cstdint>

// ---------------------------------------------------------------------------
// Problem constants
// ---------------------------------------------------------------------------
#define BATCH   512
#define NTOK    196
#define DIM     512
#define HEADS   8
#define HDIM    64
#define MROWS   (BATCH * NTOK)
#define WIN     14
#define SCALE_F 0.125f

// ---------------------------------------------------------------------------
// Scratch: single-precision fp16 operands
// ---------------------------------------------------------------------------
__device__ __half g_x16  [(size_t)MROWS * DIM];
__device__ __half g_wq16 [(size_t)DIM * 3 * DIM];
__device__ __half g_wp16 [(size_t)DIM * DIM];
__device__ __half g_qkv16[(size_t)MROWS * 3 * DIM];
__device__ __half g_at16 [(size_t)MROWS * DIM];
__device__ float  g_bias [HEADS * NTOK * NTOK];

// ---------------------------------------------------------------------------
// Fast exp (MUFU-free)
// ---------------------------------------------------------------------------
__device__ __forceinline__ float fast_exp(float x) {
    float t = x * 1.4426950408889634f;
    t = fmaxf(t, -126.0f);
    float fi = floorf(t);
    float f  = t - fi;
    float p = 1.5413220e-4f;
    p = fmaf(p, f, 1.3333558e-3f);
    p = fmaf(p, f, 9.6181291e-3f);
    p = fmaf(p, f, 5.5504109e-2f);
    p = fmaf(p, f, 2.4022651e-1f);
    p = fmaf(p, f, 6.9314718e-1f);
    p = fmaf(p, f, 1.0f);
    int ei = (int)fi;
    float sc = __int_as_float((unsigned)(ei + 127) << 23);
    return p * sc;
}

// ---------------------------------------------------------------------------
// Primitives
// ---------------------------------------------------------------------------
__device__ __forceinline__ void mma_fp16(
    float& c0, float& c1, float& c2, float& c3,
    uint32_t a0, uint32_t a1, uint32_t a2, uint32_t a3,
    uint32_t b0, uint32_t b1)
{
    asm volatile(
        "mma.sync.aligned.m16n8k16.row.col.f32.f16.f16.f32 "
        "{%0,%1,%2,%3}, {%4,%5,%6,%7}, {%8,%9}, {%0,%1,%2,%3};\n"
        : "+f"(c0), "+f"(c1), "+f"(c2), "+f"(c3)
        : "r"(a0), "r"(a1), "r"(a2), "r"(a3), "r"(b0), "r"(b1));
}

#define LDSM_X4(r0,r1,r2,r3,addr) \
    asm volatile("ldmatrix.sync.aligned.m8n8.x4.shared.b16 {%0,%1,%2,%3}, [%4];" \
        : "=r"(r0),"=r"(r1),"=r"(r2),"=r"(r3) : "r"(addr))

#define LDSM_X4_T(r0,r1,r2,r3,addr) \
    asm volatile("ldmatrix.sync.aligned.m8n8.x4.trans.shared.b16 {%0,%1,%2,%3}, [%4];" \
        : "=r"(r0),"=r"(r1),"=r"(r2),"=r"(r3) : "r"(addr))

#define CP_A16(dst, src) \
    asm volatile("cp.async.cg.shared.global [%0], [%1], 16;" :: "r"(dst), "l"(src))
#define CP_COMMIT() asm volatile("cp.async.commit_group;")
#define CP_WAIT0()  asm volatile("cp.async.wait_group 0;")
#define CP_WAIT1()  asm volatile("cp.async.wait_group 1;")

__device__ __forceinline__ uint32_t pack_h2(float a, float b) {
    __half2 t = __floats2half2_rn(a, b);
    return *(uint32_t*)&t;
}

// ---------------------------------------------------------------------------
// Converter: fp32 -> fp16
// ---------------------------------------------------------------------------
__global__ void convert_f16_kernel(const float* __restrict__ in,
                                   __half* __restrict__ out, int n4)
{
    int i = blockIdx.x * blockDim.x + threadIdx.x;
    if (i >= n4) return;
    float4 v = ((const float4*)in)[i];
    ((uint2*)out)[i] = make_uint2(pack_h2(v.x, v.y), pack_h2(v.z, v.w));
}

// ---------------------------------------------------------------------------
// Bias gather
// ---------------------------------------------------------------------------
__global__ void bias_gather_kernel(const float* __restrict__ table) {
    int idx = blockIdx.x * blockDim.x + threadIdx.x;
    if (idx >= NTOK * NTOK) return;
    int i = idx / NTOK, j = idx % NTOK;
    int ri = i / WIN, ci = i % WIN;
    int rj = j / WIN, cj = j % WIN;
    int t = (ri - rj + WIN - 1) * (2 * WIN - 1) + (ci - cj + WIN - 1);
#pragma unroll
    for (int h = 0; h < HEADS; h++)
        g_bias[h * (NTOK * NTOK) + idx] = table[t * HEADS + h];
}

// ---------------------------------------------------------------------------
// fp16 mma.sync GEMM (unchanged from R10 — measured good).
// ---------------------------------------------------------------------------
#define KT    64
#define KSA   72
#define KSB2  264
#define A_SZ  (128 * KSA)
#define B_SZ2 (KT * KSB2)
#define BUFSZ (A_SZ + B_SZ2)
#define NBUF  3
#define GEMM_SMEM_BYTES (NBUF * BUFSZ * 2)

__device__ __forceinline__ void gemm_stage(
    uint32_t base, int bufo,
    const __half* A16, const __half* B16,
    int row0, int col0, int k0, int K, int N, int tid)
{
#pragma unroll
    for (int s = 0; s < 2; s++) {
        int id = tid + s * 512;
        int r = id >> 3, c = (id & 7) * 8;
        size_t g = (size_t)(row0 + r) * K + k0 + c;
        CP_A16(base + 2 * (bufo + r * KSA + c), A16 + g);
    }
#pragma unroll
    for (int s = 0; s < 4; s++) {
        int id = tid + s * 512;
        int k = id >> 5, n = (id & 31) * 8;
        size_t g = (size_t)(k0 + k) * N + col0 + n;
        CP_A16(base + 2 * (bufo + A_SZ + k * KSB2 + n), B16 + g);
    }
}

__global__ __launch_bounds__(512, 1) void gemm_f16_kernel(
    const __half* __restrict__ A16, const __half* __restrict__ B16,
    const float* __restrict__ bias,
    float* __restrict__ C, __half* __restrict__ C16,
    int M, int N, int K, int out_f16)
{
    extern __shared__ __half sm[];
    const uint32_t base = (uint32_t)__cvta_generic_to_shared(sm);

    const int tid  = threadIdx.x;
    const int warp = tid >> 5;
    const int lane = tid & 31;
    const int wm = warp & 1;
    const int wn = warp >> 1;
    const int row0 = blockIdx.y * 128;
    const int col0 = blockIdx.x * 256;

    const int aBase = (wm * 64 + (lane & 15)) * KSA + (lane >> 4) * 8;
    const int bBase = (((lane >> 3) & 1) * 8 + (lane & 7)) * KSB2
                    + wn * 32 + (lane >> 4) * 8;

    float acc[4][4][4];
#pragma unroll
    for (int i = 0; i < 4; i++)
#pragma unroll
        for (int j = 0; j < 4; j++)
#pragma unroll
            for (int r = 0; r < 4; r++) acc[i][j][r] = 0.0f;

    const int nkt = K / KT;
    gemm_stage(base, 0 * BUFSZ, A16, B16, row0, col0, 0,  K, N, tid); CP_COMMIT();
    gemm_stage(base, 1 * BUFSZ, A16, B16, row0, col0, KT, K, N, tid); CP_COMMIT();

    int buf = 0;
    for (int kt = 0; kt < nkt; kt++) {
        const int bufo = buf * BUFSZ;
        const int oA = bufo;
        const int oB = bufo + A_SZ;

        CP_WAIT1();
        __syncthreads();

        if (kt + 2 < nkt) {
            int nb = buf + 2; if (nb >= 3) nb -= 3;
            gemm_stage(base, nb * BUFSZ, A16, B16,
                       row0, col0, (kt + 2) * KT, K, N, tid);
        }
        CP_COMMIT();

#pragma unroll
        for (int kk = 0; kk < KT; kk += 16) {
            uint32_t bh[4][2];
#pragma unroll
            for (int p = 0; p < 2; p++) {
                uint32_t r0, r1, r2, r3;
                uint32_t addr = base + 2 * (oB + bBase + kk * KSB2 + p * 16);
                LDSM_X4_T(r0, r1, r2, r3, addr);
                bh[2*p][0] = r0; bh[2*p][1] = r1; bh[2*p+1][0] = r2; bh[2*p+1][1] = r3;
            }
#pragma unroll
            for (int mt = 0; mt < 4; mt++) {
                uint32_t a0, a1, a2, a3;
                uint32_t addr = base + 2 * (oA + aBase + mt * 16 * KSA + kk);
                LDSM_X4(a0, a1, a2, a3, addr);
#pragma unroll
                for (int nt = 0; nt < 4; nt++)
                    mma_fp16(acc[mt][nt][0], acc[mt][nt][1], acc[mt][nt][2], acc[mt][nt][3],
                             a0, a1, a2, a3, bh[nt][0], bh[nt][1]);
            }
        }
        if (++buf == 3) buf = 0;
    }

#pragma unroll
    for (int mt = 0; mt < 4; mt++) {
        const int r0 = row0 + wm * 64 + mt * 16 + (lane >> 2);
#pragma unroll
        for (int nt = 0; nt < 4; nt++) {
            const int c = col0 + wn * 32 + nt * 8 + (lane & 3) * 2;
            float b0 = __ldg(bias + c), b1 = __ldg(bias + c + 1);
            float v0 = acc[mt][nt][0] + b0, v1 = acc[mt][nt][1] + b1;
            float v2 = acc[mt][nt][2] + b0, v3 = acc[mt][nt][3] + b1;
            if (out_f16) {
                *(uint32_t*)(C16 + (size_t)r0 * N + c)       = pack_h2(v0, v1);
                *(uint32_t*)(C16 + (size_t)(r0 + 8) * N + c) = pack_h2(v2, v3);
            } else {
                *(float2*)(C + (size_t)r0 * N + c)       = make_float2(v0, v1);
                *(float2*)(C + (size_t)(r0 + 8) * N + c) = make_float2(v2, v3);
            }
        }
    }
}

// ---------------------------------------------------------------------------
// fp16 window attention v3: 2 CTAs per (b,h) (query halves of 112 rows),
// 128 threads = 4 warps x 32 rows. Flash-style loop over 13 key-blocks of 16:
// each K/V fragment load serves 32 query rows (half the LDSM traffic of v2).
// S is a 16-reg transient; Q fragments loaded once.
// ---------------------------------------------------------------------------
#define QS      72
#define QROWS   112
#define QPAD    128
#define KROWS   208
#define NKB     13
#define QSZ3    (QPAD * QS)
#define KSZ3    (KROWS * QS)
#define ATT_SMEM_BYTES ((QSZ3 + 2 * KSZ3) * 2)   // 78336 B

__global__ __launch_bounds__(128, 2) void attn_mma_kernel() {
    extern __shared__ __half smA[];
    const uint32_t base = (uint32_t)__cvta_generic_to_shared(smA);
    const uint32_t uQ = base;
    const uint32_t uK = base + 2 * QSZ3;
    const uint32_t uV = base + 2 * (QSZ3 + KSZ3);

    const int h = blockIdx.x;
    const int b = blockIdx.y;
    const int qrow0 = blockIdx.z * QROWS;       // 0 or 112
    const int tid = threadIdx.x;
    const size_t rowbase = (size_t)b * NTOK;
    const int qvalid = min(QROWS, NTOK - qrow0); // 112 or 84

    // zero pads: Q local rows [qvalid,128), K/V rows [196,208)
    {
        uint2 z = make_uint2(0u, 0u);
        for (int t = tid; t < (QPAD - qvalid) * 16; t += 128) {
            int r = qvalid + (t >> 4), c = (t & 15) * 4;
            *(uint2*)&smA[r * QS + c] = z;
        }
        for (int t = tid; t < 12 * 16; t += 128) {
            int r = 196 + (t >> 4), c = (t & 15) * 4;
            *(uint2*)&smA[QSZ3 + r * QS + c] = z;
            *(uint2*)&smA[QSZ3 + KSZ3 + r * QS + c] = z;
        }
    }

    // cp.async stage Q half + full K/V
    {
        const size_t gbase = rowbase * (3 * DIM) + h * HDIM;
        for (int t = tid; t < qvalid * 8; t += 128) {
            int r = t >> 3, c = (t & 7) * 8;
            size_t g = gbase + (size_t)(qrow0 + r) * (3 * DIM) + c;
            CP_A16(uQ + 2 * (r * QS + c), g_qkv16 + g);
        }
        for (int t = tid; t < NTOK * 8; t += 128) {
            int r = t >> 3, c = (t & 7) * 8;
            size_t g = gbase + (size_t)r * (3 * DIM) + c;
            uint32_t d = 2 * (r * QS + c);
            CP_A16(uK + d, g_qkv16 + g + DIM);
            CP_A16(uV + d, g_qkv16 + g + 2 * DIM);
        }
        CP_COMMIT();
        CP_WAIT0();
    }
    __syncthreads();

    const int warp = tid >> 5;
    const int lane = tid & 31;
    const int rows0 = warp * 32;                 // local (0..96)

    // global query rows per M-tile
    int rA0 = qrow0 + rows0 + (lane >> 2);       // mt 0
    int rA1 = rA0 + 16;                          // mt 1
    const int rAc0 = min(rA0,      NTOK - 1);
    const int rBc0 = min(rA0 + 8,  NTOK - 1);
    const int rAc1 = min(rA1,      NTOK - 1);
    const int rBc1 = min(rA1 + 8,  NTOK - 1);
    const float* biasH = g_bias + h * (NTOK * NTOK);

    // Q fragments: [mt][ks]
    uint32_t qh[2][4][4];
#pragma unroll
    for (int mt = 0; mt < 2; mt++)
#pragma unroll
        for (int ks = 0; ks < 4; ks++) {
            uint32_t addr = uQ + 2 * ((rows0 + mt * 16 + (lane & 15)) * QS
                                      + (lane >> 4) * 8 + ks * 16);
            LDSM_X4(qh[mt][ks][0], qh[mt][ks][1], qh[mt][ks][2], qh[mt][ks][3], addr);
        }

    float o[2][8][4];
#pragma unroll
    for (int mt = 0; mt < 2; mt++)
#pragma unroll
        for (int i = 0; i < 8; i++)
#pragma unroll
            for (int r = 0; r < 4; r++) o[mt][i][r] = 0.0f;
    float sums[2][2] = {{0.f, 0.f}, {0.f, 0.f}};

    const int kRow = lane & 15;
    const int kCol = (lane >> 4) * 8;
    const int vRow = ((lane >> 3) & 1) * 8 + (lane & 7);

    for (int kb = 0; kb < NKB; kb++) {
        const int j = kb * 16;

        // K fragments for this 16-key block (serve both M-tiles)
        uint32_t kh[4][4];
#pragma unroll
        for (int ks = 0; ks < 4; ks++) {
            uint32_t addr = uK + 2 * ((j + kRow) * QS + kCol + ks * 16);
            LDSM_X4(kh[ks][0], kh[ks][1], kh[ks][2], kh[ks][3], addr);
        }

        // S = Q K^T (transient, 16 regs)
        float s[2][2][4];
#pragma unroll
        for (int mt = 0; mt < 2; mt++)
#pragma unroll
            for (int nt = 0; nt < 2; nt++)
#pragma unroll
                for (int r = 0; r < 4; r++) s[mt][nt][r] = 0.0f;
#pragma unroll
        for (int mt = 0; mt < 2; mt++)
#pragma unroll
            for (int ks = 0; ks < 4; ks++) {
                mma_fp16(s[mt][0][0], s[mt][0][1], s[mt][0][2], s[mt][0][3],
                         qh[mt][ks][0], qh[mt][ks][1], qh[mt][ks][2], qh[mt][ks][3],
                         kh[ks][0], kh[ks][2]);
                mma_fp16(s[mt][1][0], s[mt][1][1], s[mt][1][2], s[mt][1][3],
                         qh[mt][ks][0], qh[mt][ks][1], qh[mt][ks][2], qh[mt][ks][3],
                         kh[ks][1], kh[ks][3]);
            }

        // bias + mask + exp + pack
        uint32_t pA[2][2], pB[2][2];
#pragma unroll
        for (int mt = 0; mt < 2; mt++) {
            const int rac = mt ? rAc1 : rAc0;
            const int rbc = mt ? rBc1 : rBc0;
#pragma unroll
            for (int nt = 0; nt < 2; nt++) {
                int col = j + nt * 8 + (lane & 3) * 2;
                int colc = min(col, NTOK - 2);
                float2 bA = *(const float2*)(biasH + rac * NTOK + colc);
                float2 bB = *(const float2*)(biasH + rbc * NTOK + colc);
                float v0 = fmaf(s[mt][nt][0], SCALE_F, bA.x);
                float v1 = fmaf(s[mt][nt][1], SCALE_F, bA.y);
                float v2 = fmaf(s[mt][nt][2], SCALE_F, bB.x);
                float v3 = fmaf(s[mt][nt][3], SCALE_F, bB.y);
                if (col     >= NTOK) { v0 = -1e30f; v2 = -1e30f; }
                if (col + 1 >= NTOK) { v1 = -1e30f; v3 = -1e30f; }
                float p0 = fast_exp(v0);
                float p1 = fast_exp(v1);
                float p2 = fast_exp(v2);
                float p3 = fast_exp(v3);
                sums[mt][0] += p0 + p1;
                sums[mt][1] += p2 + p3;
                pA[mt][nt] = pack_h2(p0, p1);
                pB[mt][nt] = pack_h2(p2, p3);
            }
        }

        // O += P V  (V fragments shared across both M-tiles)
#pragma unroll
        for (int vn = 0; vn < 4; vn++) {
            uint32_t vh0, vh1, vh2, vh3;
            uint32_t addr = uV + 2 * ((j + vRow) * QS + vn * 16 + (lane >> 4) * 8);
            LDSM_X4_T(vh0, vh1, vh2, vh3, addr);
#pragma unroll
            for (int mt = 0; mt < 2; mt++) {
                float* o0 = o[mt][2 * vn];
                float* o1 = o[mt][2 * vn + 1];
                mma_fp16(o0[0], o0[1], o0[2], o0[3],
                         pA[mt][0], pB[mt][0], pA[mt][1], pB[mt][1], vh0, vh1);
                mma_fp16(o1[0], o1[1], o1[2], o1[3],
                         pA[mt][0], pB[mt][0], pA[mt][1], pB[mt][1], vh2, vh3);
            }
        }
    }

    // finalize
    const size_t obase = rowbase * DIM + h * HDIM;
#pragma unroll
    for (int mt = 0; mt < 2; mt++) {
        float s0 = sums[mt][0], s1 = sums[mt][1];
        s0 += __shfl_xor_sync(0xffffffff, s0, 1);
        s0 += __shfl_xor_sync(0xffffffff, s0, 2);
        s1 += __shfl_xor_sync(0xffffffff, s1, 1);
        s1 += __shfl_xor_sync(0xffffffff, s1, 2);
        float r0s = 1.0f / s0;
        float r1s = 1.0f / s1;
        const int ra = mt ? rA1 : rA0;
        const int rb = ra + 8;
#pragma unroll
        for (int nt = 0; nt < 8; nt++) {
            int col = nt * 8 + (lane & 3) * 2;
            if (ra < NTOK)
                *(uint32_t*)(g_at16 + obase + (size_t)ra * DIM + col) =
                    pack_h2(o[mt][nt][0] * r0s, o[mt][nt][1] * r0s);
            if (rb < NTOK)
                *(uint32_t*)(g_at16 + obase + (size_t)rb * DIM + col) =
                    pack_h2(o[mt][nt][2] * r1s, o[mt][nt][3] * r1s);
        }
    }
}

// ---------------------------------------------------------------------------
// Launch
// ---------------------------------------------------------------------------
extern "C" void kernel_launch(void* const* d_in, const int* in_sizes, int n_in,
                              void* d_out, int out_size)
{
    const float* x          = (const float*)d_in[0];
    const float* w_qkv      = (const float*)d_in[1];
    const float* b_qkv      = (const float*)d_in[2];
    const float* w_proj     = (const float*)d_in[3];
    const float* b_proj     = (const float*)d_in[4];
    const float* bias_table = (const float*)d_in[5];
    float* out              = (float*)d_out;

    __half *x16, *wq16, *wp16, *qkv16, *at16;
    cudaGetSymbolAddress((void**)&x16,   g_x16);
    cudaGetSymbolAddress((void**)&wq16,  g_wq16);
    cudaGetSymbolAddress((void**)&wp16,  g_wp16);
    cudaGetSymbolAddress((void**)&qkv16, g_qkv16);
    cudaGetSymbolAddress((void**)&at16,  g_at16);

    cudaFuncSetAttribute(gemm_f16_kernel,
                         cudaFuncAttributeMaxDynamicSharedMemorySize,
                         GEMM_SMEM_BYTES);
    cudaFuncSetAttribute(attn_mma_kernel,
                         cudaFuncAttributeMaxDynamicSharedMemorySize,
                         ATT_SMEM_BYTES);

    bias_gather_kernel<<<(NTOK * NTOK + 255) / 256, 256>>>(bias_table);

    {   // fp32 -> fp16 conversions
        int n4 = MROWS * DIM / 4;
        convert_f16_kernel<<<(n4 + 255) / 256, 256>>>(x, x16, n4);
        n4 = DIM * 3 * DIM / 4;
        convert_f16_kernel<<<(n4 + 255) / 256, 256>>>(w_qkv, wq16, n4);
        n4 = DIM * DIM / 4;
        convert_f16_kernel<<<(n4 + 255) / 256, 256>>>(w_proj, wp16, n4);
    }

    {   // QKV GEMM -> fp16 output
        dim3 grid(3 * DIM / 256, MROWS / 128);
        gemm_f16_kernel<<<grid, 512, GEMM_SMEM_BYTES>>>(
            x16, wq16, b_qkv, nullptr, qkv16, MROWS, 3 * DIM, DIM, 1);
    }

    {   // window attention: 2 CTAs per (h,b), flash-style, M=32 warps
        dim3 grid(HEADS, BATCH, 2);
        attn_mma_kernel<<<grid, 128, ATT_SMEM_BYTES>>>();
    }

    {   // output projection -> fp32
        dim3 grid(DIM / 256, MROWS / 128);
        gemm_f16_kernel<<<grid, 512, GEMM_SMEM_BYTES>>>(
            at16, wp16, b_proj, out, nullptr, MROWS, DIM, DIM, 0);
    }
}

// round 13
// speedup vs baseline: 1.0716x; 1.0716x over previous
#include <cuda_runtime.h>
#include <cuda_fp16.h>
#include <cstdint>

// ---------------------------------------------------------------------------
// Problem constants
// ---------------------------------------------------------------------------
#define BATCH   512
#define NTOK    196
#define DIM     512
#define HEADS   8
#define HDIM    64
#define MROWS   (BATCH * NTOK)
#define WIN     14
#define SCALE_F 0.125f

// ---------------------------------------------------------------------------
// Scratch: single-precision fp16 operands
// ---------------------------------------------------------------------------
__device__ __half g_x16  [(size_t)MROWS * DIM];
__device__ __half g_wq16 [(size_t)DIM * 3 * DIM];
__device__ __half g_wp16 [(size_t)DIM * DIM];
__device__ __half g_qkv16[(size_t)MROWS * 3 * DIM];
__device__ __half g_at16 [(size_t)MROWS * DIM];
__device__ float  g_bias [HEADS * NTOK * NTOK];

// ---------------------------------------------------------------------------
// Fast exp (MUFU-free)
// ---------------------------------------------------------------------------
__device__ __forceinline__ float fast_exp(float x) {
    float t = x * 1.4426950408889634f;
    t = fmaxf(t, -126.0f);
    float fi = floorf(t);
    float f  = t - fi;
    float p = 1.5413220e-4f;
    p = fmaf(p, f, 1.3333558e-3f);
    p = fmaf(p, f, 9.6181291e-3f);
    p = fmaf(p, f, 5.5504109e-2f);
    p = fmaf(p, f, 2.4022651e-1f);
    p = fmaf(p, f, 6.9314718e-1f);
    p = fmaf(p, f, 1.0f);
    int ei = (int)fi;
    float sc = __int_as_float((unsigned)(ei + 127) << 23);
    return p * sc;
}

// ---------------------------------------------------------------------------
// Primitives
// ---------------------------------------------------------------------------
__device__ __forceinline__ void mma_fp16(
    float& c0, float& c1, float& c2, float& c3,
    uint32_t a0, uint32_t a1, uint32_t a2, uint32_t a3,
    uint32_t b0, uint32_t b1)
{
    asm volatile(
        "mma.sync.aligned.m16n8k16.row.col.f32.f16.f16.f32 "
        "{%0,%1,%2,%3}, {%4,%5,%6,%7}, {%8,%9}, {%0,%1,%2,%3};\n"
        : "+f"(c0), "+f"(c1), "+f"(c2), "+f"(c3)
        : "r"(a0), "r"(a1), "r"(a2), "r"(a3), "r"(b0), "r"(b1));
}

#define LDSM_X4(r0,r1,r2,r3,addr) \
    asm volatile("ldmatrix.sync.aligned.m8n8.x4.shared.b16 {%0,%1,%2,%3}, [%4];" \
        : "=r"(r0),"=r"(r1),"=r"(r2),"=r"(r3) : "r"(addr))

#define LDSM_X4_T(r0,r1,r2,r3,addr) \
    asm volatile("ldmatrix.sync.aligned.m8n8.x4.trans.shared.b16 {%0,%1,%2,%3}, [%4];" \
        : "=r"(r0),"=r"(r1),"=r"(r2),"=r"(r3) : "r"(addr))

#define CP_A16(dst, src) \
    asm volatile("cp.async.cg.shared.global [%0], [%1], 16;" :: "r"(dst), "l"(src))
#define CP_COMMIT() asm volatile("cp.async.commit_group;")
#define CP_WAIT0()  asm volatile("cp.async.wait_group 0;")
#define CP_WAIT1()  asm volatile("cp.async.wait_group 1;")

__device__ __forceinline__ uint32_t pack_h2(float a, float b) {
    __half2 t = __floats2half2_rn(a, b);
    return *(uint32_t*)&t;
}

// ---------------------------------------------------------------------------
// Converter: fp32 -> fp16
// ---------------------------------------------------------------------------
__global__ void convert_f16_kernel(const float* __restrict__ in,
                                   __half* __restrict__ out, int n4)
{
    int i = blockIdx.x * blockDim.x + threadIdx.x;
    if (i >= n4) return;
    float4 v = ((const float4*)in)[i];
    ((uint2*)out)[i] = make_uint2(pack_h2(v.x, v.y), pack_h2(v.z, v.w));
}

// ---------------------------------------------------------------------------
// Bias gather
// ---------------------------------------------------------------------------
__global__ void bias_gather_kernel(const float* __restrict__ table) {
    int idx = blockIdx.x * blockDim.x + threadIdx.x;
    if (idx >= NTOK * NTOK) return;
    int i = idx / NTOK, j = idx % NTOK;
    int ri = i / WIN, ci = i % WIN;
    int rj = j / WIN, cj = j % WIN;
    int t = (ri - rj + WIN - 1) * (2 * WIN - 1) + (ci - cj + WIN - 1);
#pragma unroll
    for (int h = 0; h < HEADS; h++)
        g_bias[h * (NTOK * NTOK) + idx] = table[t * HEADS + h];
}

// ---------------------------------------------------------------------------
// fp16 mma.sync GEMM (unchanged from R10 — measured good).
// 128x256 CTA tile, 512 threads, K-tile 64, 3-stage cp.async ring.
// ---------------------------------------------------------------------------
#define KT    64
#define KSA   72
#define KSB2  264
#define A_SZ  (128 * KSA)
#define B_SZ2 (KT * KSB2)
#define BUFSZ (A_SZ + B_SZ2)
#define NBUF  3
#define GEMM_SMEM_BYTES (NBUF * BUFSZ * 2)

__device__ __forceinline__ void gemm_stage(
    uint32_t base, int bufo,
    const __half* A16, const __half* B16,
    int row0, int col0, int k0, int K, int N, int tid)
{
#pragma unroll
    for (int s = 0; s < 2; s++) {
        int id = tid + s * 512;
        int r = id >> 3, c = (id & 7) * 8;
        size_t g = (size_t)(row0 + r) * K + k0 + c;
        CP_A16(base + 2 * (bufo + r * KSA + c), A16 + g);
    }
#pragma unroll
    for (int s = 0; s < 4; s++) {
        int id = tid + s * 512;
        int k = id >> 5, n = (id & 31) * 8;
        size_t g = (size_t)(k0 + k) * N + col0 + n;
        CP_A16(base + 2 * (bufo + A_SZ + k * KSB2 + n), B16 + g);
    }
}

__global__ __launch_bounds__(512, 1) void gemm_f16_kernel(
    const __half* __restrict__ A16, const __half* __restrict__ B16,
    const float* __restrict__ bias,
    float* __restrict__ C, __half* __restrict__ C16,
    int M, int N, int K, int out_f16)
{
    extern __shared__ __half sm[];
    const uint32_t base = (uint32_t)__cvta_generic_to_shared(sm);

    const int tid  = threadIdx.x;
    const int warp = tid >> 5;
    const int lane = tid & 31;
    const int wm = warp & 1;
    const int wn = warp >> 1;
    const int row0 = blockIdx.y * 128;
    const int col0 = blockIdx.x * 256;

    const int aBase = (wm * 64 + (lane & 15)) * KSA + (lane >> 4) * 8;
    const int bBase = (((lane >> 3) & 1) * 8 + (lane & 7)) * KSB2
                    + wn * 32 + (lane >> 4) * 8;

    float acc[4][4][4];
#pragma unroll
    for (int i = 0; i < 4; i++)
#pragma unroll
        for (int j = 0; j < 4; j++)
#pragma unroll
            for (int r = 0; r < 4; r++) acc[i][j][r] = 0.0f;

    const int nkt = K / KT;
    gemm_stage(base, 0 * BUFSZ, A16, B16, row0, col0, 0,  K, N, tid); CP_COMMIT();
    gemm_stage(base, 1 * BUFSZ, A16, B16, row0, col0, KT, K, N, tid); CP_COMMIT();

    int buf = 0;
    for (int kt = 0; kt < nkt; kt++) {
        const int bufo = buf * BUFSZ;
        const int oA = bufo;
        const int oB = bufo + A_SZ;

        CP_WAIT1();
        __syncthreads();

        if (kt + 2 < nkt) {
            int nb = buf + 2; if (nb >= 3) nb -= 3;
            gemm_stage(base, nb * BUFSZ, A16, B16,
                       row0, col0, (kt + 2) * KT, K, N, tid);
        }
        CP_COMMIT();

#pragma unroll
        for (int kk = 0; kk < KT; kk += 16) {
            uint32_t bh[4][2];
#pragma unroll
            for (int p = 0; p < 2; p++) {
                uint32_t r0, r1, r2, r3;
                uint32_t addr = base + 2 * (oB + bBase + kk * KSB2 + p * 16);
                LDSM_X4_T(r0, r1, r2, r3, addr);
                bh[2*p][0] = r0; bh[2*p][1] = r1; bh[2*p+1][0] = r2; bh[2*p+1][1] = r3;
            }
#pragma unroll
            for (int mt = 0; mt < 4; mt++) {
                uint32_t a0, a1, a2, a3;
                uint32_t addr = base + 2 * (oA + aBase + mt * 16 * KSA + kk);
                LDSM_X4(a0, a1, a2, a3, addr);
#pragma unroll
                for (int nt = 0; nt < 4; nt++)
                    mma_fp16(acc[mt][nt][0], acc[mt][nt][1], acc[mt][nt][2], acc[mt][nt][3],
                             a0, a1, a2, a3, bh[nt][0], bh[nt][1]);
            }
        }
        if (++buf == 3) buf = 0;
    }

#pragma unroll
    for (int mt = 0; mt < 4; mt++) {
        const int r0 = row0 + wm * 64 + mt * 16 + (lane >> 2);
#pragma unroll
        for (int nt = 0; nt < 4; nt++) {
            const int c = col0 + wn * 32 + nt * 8 + (lane & 3) * 2;
            float b0 = __ldg(bias + c), b1 = __ldg(bias + c + 1);
            float v0 = acc[mt][nt][0] + b0, v1 = acc[mt][nt][1] + b1;
            float v2 = acc[mt][nt][2] + b0, v3 = acc[mt][nt][3] + b1;
            if (out_f16) {
                *(uint32_t*)(C16 + (size_t)r0 * N + c)       = pack_h2(v0, v1);
                *(uint32_t*)(C16 + (size_t)(r0 + 8) * N + c) = pack_h2(v2, v3);
            } else {
                *(float2*)(C + (size_t)r0 * N + c)       = make_float2(v0, v1);
                *(float2*)(C + (size_t)(r0 + 8) * N + c) = make_float2(v2, v3);
            }
        }
    }
}

// ---------------------------------------------------------------------------
// fp16 window attention (R11 structure: 2 CTAs per (b,h), 224 threads =
// 7 warps x 16 rows). Chunking trimmed: chunk0 = 14 ntiles (cols 0..111),
// chunk1 = 12 ntiles (cols 112..207) — only 12 masked columns vs 28.
// K/V padded to 208 rows.
// ---------------------------------------------------------------------------
#define QS      72
#define QROWS   112
#define NPAD    208
#define QSZ2    (QROWS * QS)         // 8064 elems
#define KSZ     (NPAD * QS)          // 14976 elems
#define ATT_SMEM_BYTES ((QSZ2 + 2 * KSZ) * 2)   // 76032 B

__global__ __launch_bounds__(224, 2) void attn_mma_kernel() {
    extern __shared__ __half smA[];
    const uint32_t base = (uint32_t)__cvta_generic_to_shared(smA);
    const uint32_t uQ = base;
    const uint32_t uK = base + 2 * QSZ2;
    const uint32_t uV = base + 2 * (QSZ2 + KSZ);

    const int h = blockIdx.x;
    const int b = blockIdx.y;
    const int qrow0 = blockIdx.z * QROWS;     // 0 or 112
    const int tid = threadIdx.x;
    const size_t rowbase = (size_t)b * NTOK;

    // zero pads: Q local rows with global row >= 196; K/V rows 196..207
    {
        uint2 z = make_uint2(0u, 0u);
        if (qrow0 + QROWS > NTOK) {
            for (int t = tid; t < (qrow0 + QROWS - NTOK) * 16; t += 224) {
                int r = (NTOK - qrow0) + (t >> 4), c = (t & 15) * 4;
                *(uint2*)&smA[r * QS + c] = z;
            }
        }
        for (int t = tid; t < 12 * 16; t += 224) {
            int r = 196 + (t >> 4), c = (t & 15) * 4;
            *(uint2*)&smA[QSZ2 + r * QS + c] = z;
            *(uint2*)&smA[QSZ2 + KSZ + r * QS + c] = z;
        }
    }

    // cp.async stage Q half + full K/V
    {
        const size_t gbase = rowbase * (3 * DIM) + h * HDIM;
        const int qvalid = min(QROWS, NTOK - qrow0);   // 112 or 84
        for (int t = tid; t < qvalid * 8; t += 224) {
            int r = t >> 3, c = (t & 7) * 8;
            size_t g = gbase + (size_t)(qrow0 + r) * (3 * DIM) + c;
            CP_A16(uQ + 2 * (r * QS + c), g_qkv16 + g);
        }
        for (int t = tid; t < NTOK * 8; t += 224) {
            int r = t >> 3, c = (t & 7) * 8;
            size_t g = gbase + (size_t)r * (3 * DIM) + c;
            uint32_t d = 2 * (r * QS + c);
            CP_A16(uK + d, g_qkv16 + g + DIM);
            CP_A16(uV + d, g_qkv16 + g + 2 * DIM);
        }
        CP_COMMIT();
        CP_WAIT0();
    }
    __syncthreads();

    const int warp = tid >> 5;
    const int lane = tid & 31;
    const int rows0 = warp * 16;              // local

    float o[8][4];
#pragma unroll
    for (int i = 0; i < 8; i++)
#pragma unroll
        for (int r = 0; r < 4; r++) o[i][r] = 0.0f;
    float sum0 = 0.0f, sum1 = 0.0f;

    const int rA = qrow0 + rows0 + (lane >> 2);   // global query row
    const int rB = rA + 8;
    const int rAc = min(rA, NTOK - 1);
    const int rBc = min(rB, NTOK - 1);
    const float* biasH = g_bias + h * (NTOK * NTOK);

    const int qBase = (rows0 + (lane & 15)) * QS + (lane >> 4) * 8;
    const int kBaseRow = (lane & 15);
    const int vBaseRow = ((lane >> 3) & 1) * 8 + (lane & 7);

#pragma unroll
    for (int c = 0; c < 2; c++) {
        const int j0 = c * 112;
        const int NT = c ? 12 : 14;      // ntiles this chunk (compile-time)
        const int NP = NT / 2;           // ntile pairs

        uint32_t qh[4][4];
#pragma unroll
        for (int ks = 0; ks < 4; ks++) {
            uint32_t addr = uQ + 2 * (qBase + ks * 16);
            LDSM_X4(qh[ks][0], qh[ks][1], qh[ks][2], qh[ks][3], addr);
        }

        float s[14][4];
#pragma unroll
        for (int nt = 0; nt < NT; nt++)
#pragma unroll
            for (int r = 0; r < 4; r++) s[nt][r] = 0.0f;

#pragma unroll
        for (int ntp = 0; ntp < NP; ntp++) {
#pragma unroll
            for (int ks = 0; ks < 4; ks++) {
                uint32_t kh0, kh1, kh2, kh3;
                uint32_t addr = uK + 2 * ((j0 + ntp * 16 + kBaseRow) * QS
                                          + (lane >> 4) * 8 + ks * 16);
                LDSM_X4(kh0, kh1, kh2, kh3, addr);
                float* s0 = s[2 * ntp];
                float* s1 = s[2 * ntp + 1];
                mma_fp16(s0[0], s0[1], s0[2], s0[3],
                         qh[ks][0], qh[ks][1], qh[ks][2], qh[ks][3], kh0, kh2);
                mma_fp16(s1[0], s1[1], s1[2], s1[3],
                         qh[ks][0], qh[ks][1], qh[ks][2], qh[ks][3], kh1, kh3);
            }
        }

        // bias + mask + exp (no max subtraction — scores bounded)
        uint32_t pa[14], pb_[14];
#pragma unroll
        for (int nt = 0; nt < NT; nt++) {
            int col = j0 + nt * 8 + (lane & 3) * 2;
            int colc = min(col, NTOK - 2);
            float2 bA = *(const float2*)(biasH + rAc * NTOK + colc);
            float2 bB = *(const float2*)(biasH + rBc * NTOK + colc);
            float v0 = fmaf(s[nt][0], SCALE_F, bA.x);
            float v1 = fmaf(s[nt][1], SCALE_F, bA.y);
            float v2 = fmaf(s[nt][2], SCALE_F, bB.x);
            float v3 = fmaf(s[nt][3], SCALE_F, bB.y);
            if (col     >= NTOK) { v0 = -1e30f; v2 = -1e30f; }
            if (col + 1 >= NTOK) { v1 = -1e30f; v3 = -1e30f; }
            float p0 = fast_exp(v0);
            float p1 = fast_exp(v1);
            float p2 = fast_exp(v2);
            float p3 = fast_exp(v3);
            sum0 += p0 + p1;
            sum1 += p2 + p3;
            pa[nt]  = pack_h2(p0, p1);
            pb_[nt] = pack_h2(p2, p3);
        }

#pragma unroll
        for (int q = 0; q < NP; q++) {
            uint32_t a0 = pa[2*q], a1 = pb_[2*q], a2 = pa[2*q+1], a3 = pb_[2*q+1];
#pragma unroll
            for (int vn = 0; vn < 4; vn++) {
                uint32_t vh0, vh1, vh2, vh3;
                uint32_t addr = uV + 2 * ((j0 + q * 16 + vBaseRow) * QS
                                          + vn * 16 + (lane >> 4) * 8);
                LDSM_X4_T(vh0, vh1, vh2, vh3, addr);
                float* o0 = o[2 * vn];
                float* o1 = o[2 * vn + 1];
                mma_fp16(o0[0], o0[1], o0[2], o0[3], a0, a1, a2, a3, vh0, vh1);
                mma_fp16(o1[0], o1[1], o1[2], o1[3], a0, a1, a2, a3, vh2, vh3);
            }
        }
    }

    sum0 += __shfl_xor_sync(0xffffffff, sum0, 1);
    sum0 += __shfl_xor_sync(0xffffffff, sum0, 2);
    sum1 += __shfl_xor_sync(0xffffffff, sum1, 1);
    sum1 += __shfl_xor_sync(0xffffffff, sum1, 2);
    float r0s = 1.0f / sum0;
    float r1s = 1.0f / sum1;

    const size_t obase = rowbase * DIM + h * HDIM;
#pragma unroll
    for (int nt = 0; nt < 8; nt++) {
        int col = nt * 8 + (lane & 3) * 2;
        if (rA < NTOK)
            *(uint32_t*)(g_at16 + obase + (size_t)rA * DIM + col) =
                pack_h2(o[nt][0] * r0s, o[nt][1] * r0s);
        if (rB < NTOK)
            *(uint32_t*)(g_at16 + obase + (size_t)rB * DIM + col) =
                pack_h2(o[nt][2] * r1s, o[nt][3] * r1s);
    }
}

// ---------------------------------------------------------------------------
// Launch
// ---------------------------------------------------------------------------
extern "C" void kernel_launch(void* const* d_in, const int* in_sizes, int n_in,
                              void* d_out, int out_size)
{
    const float* x          = (const float*)d_in[0];
    const float* w_qkv      = (const float*)d_in[1];
    const float* b_qkv      = (const float*)d_in[2];
    const float* w_proj     = (const float*)d_in[3];
    const float* b_proj     = (const float*)d_in[4];
    const float* bias_table = (const float*)d_in[5];
    float* out              = (float*)d_out;

    __half *x16, *wq16, *wp16, *qkv16, *at16;
    cudaGetSymbolAddress((void**)&x16,   g_x16);
    cudaGetSymbolAddress((void**)&wq16,  g_wq16);
    cudaGetSymbolAddress((void**)&wp16,  g_wp16);
    cudaGetSymbolAddress((void**)&qkv16, g_qkv16);
    cudaGetSymbolAddress((void**)&at16,  g_at16);

    cudaFuncSetAttribute(gemm_f16_kernel,
                         cudaFuncAttributeMaxDynamicSharedMemorySize,
                         GEMM_SMEM_BYTES);
    cudaFuncSetAttribute(attn_mma_kernel,
                         cudaFuncAttributeMaxDynamicSharedMemorySize,
                         ATT_SMEM_BYTES);

    bias_gather_kernel<<<(NTOK * NTOK + 255) / 256, 256>>>(bias_table);

    {   // fp32 -> fp16 conversions
        int n4 = MROWS * DIM / 4;
        convert_f16_kernel<<<(n4 + 255) / 256, 256>>>(x, x16, n4);
        n4 = DIM * 3 * DIM / 4;
        convert_f16_kernel<<<(n4 + 255) / 256, 256>>>(w_qkv, wq16, n4);
        n4 = DIM * DIM / 4;
        convert_f16_kernel<<<(n4 + 255) / 256, 256>>>(w_proj, wp16, n4);
    }

    {   // QKV GEMM -> fp16 output
        dim3 grid(3 * DIM / 256, MROWS / 128);
        gemm_f16_kernel<<<grid, 512, GEMM_SMEM_BYTES>>>(
            x16, wq16, b_qkv, nullptr, qkv16, MROWS, 3 * DIM, DIM, 1);
    }

    {   // window attention: 2 CTAs per (h,b), each 112 query rows
        dim3 grid(HEADS, BATCH, 2);
        attn_mma_kernel<<<grid, 224, ATT_SMEM_BYTES>>>();
    }

    {   // output projection -> fp32
        dim3 grid(DIM / 256, MROWS / 128);
        gemm_f16_kernel<<<grid, 512, GEMM_SMEM_BYTES>>>(
            at16, wp16, b_proj, out, nullptr, MROWS, DIM, DIM, 0);
    }
}

// round 15
// speedup vs baseline: 1.1035x; 1.0297x over previous
#include <cuda_runtime.h>
#include <cuda_fp16.h>
#include <cstdint>

// ---------------------------------------------------------------------------
// Problem constants
// ---------------------------------------------------------------------------
#define BATCH   512
#define NTOK    196
#define DIM     512
#define HEADS   8
#define HDIM    64
#define MROWS   (BATCH * NTOK)
#define WIN     14
#define SCALE_F 0.125f

// ---------------------------------------------------------------------------
// Scratch: single-precision fp16 operands
// ---------------------------------------------------------------------------
__device__ __half g_x16  [(size_t)MROWS * DIM];
__device__ __half g_wq16 [(size_t)DIM * 3 * DIM];
__device__ __half g_wp16 [(size_t)DIM * DIM];
__device__ __half g_qkv16[(size_t)MROWS * 3 * DIM];
__device__ __half g_at16 [(size_t)MROWS * DIM];
__device__ __half g_bias16[HEADS * NTOK * NTOK];

// ---------------------------------------------------------------------------
// Fast exp (MUFU-free)
// ---------------------------------------------------------------------------
__device__ __forceinline__ float fast_exp(float x) {
    float t = x * 1.4426950408889634f;
    t = fmaxf(t, -126.0f);
    float fi = floorf(t);
    float f  = t - fi;
    float p = 1.5413220e-4f;
    p = fmaf(p, f, 1.3333558e-3f);
    p = fmaf(p, f, 9.6181291e-3f);
    p = fmaf(p, f, 5.5504109e-2f);
    p = fmaf(p, f, 2.4022651e-1f);
    p = fmaf(p, f, 6.9314718e-1f);
    p = fmaf(p, f, 1.0f);
    int ei = (int)fi;
    float sc = __int_as_float((unsigned)(ei + 127) << 23);
    return p * sc;
}

// ---------------------------------------------------------------------------
// Primitives
// ---------------------------------------------------------------------------
__device__ __forceinline__ void mma_fp16(
    float& c0, float& c1, float& c2, float& c3,
    uint32_t a0, uint32_t a1, uint32_t a2, uint32_t a3,
    uint32_t b0, uint32_t b1)
{
    asm volatile(
        "mma.sync.aligned.m16n8k16.row.col.f32.f16.f16.f32 "
        "{%0,%1,%2,%3}, {%4,%5,%6,%7}, {%8,%9}, {%0,%1,%2,%3};\n"
        : "+f"(c0), "+f"(c1), "+f"(c2), "+f"(c3)
        : "r"(a0), "r"(a1), "r"(a2), "r"(a3), "r"(b0), "r"(b1));
}

#define LDSM_X4(r0,r1,r2,r3,addr) \
    asm volatile("ldmatrix.sync.aligned.m8n8.x4.shared.b16 {%0,%1,%2,%3}, [%4];" \
        : "=r"(r0),"=r"(r1),"=r"(r2),"=r"(r3) : "r"(addr))

#define LDSM_X4_T(r0,r1,r2,r3,addr) \
    asm volatile("ldmatrix.sync.aligned.m8n8.x4.trans.shared.b16 {%0,%1,%2,%3}, [%4];" \
        : "=r"(r0),"=r"(r1),"=r"(r2),"=r"(r3) : "r"(addr))

#define CP_A16(dst, src) \
    asm volatile("cp.async.cg.shared.global [%0], [%1], 16;" :: "r"(dst), "l"(src))
#define CP_COMMIT() asm volatile("cp.async.commit_group;")
#define CP_WAIT0()  asm volatile("cp.async.wait_group 0;")
#define CP_WAIT1()  asm volatile("cp.async.wait_group 1;")

__device__ __forceinline__ uint32_t pack_h2(float a, float b) {
    __half2 t = __floats2half2_rn(a, b);
    return *(uint32_t*)&t;
}

__device__ __forceinline__ float2 unpack_h2(uint32_t v) {
    return __half22float2(*(__half2*)&v);
}

// ---------------------------------------------------------------------------
// Converter: fp32 -> fp16
// ---------------------------------------------------------------------------
__global__ void convert_f16_kernel(const float* __restrict__ in,
                                   __half* __restrict__ out, int n4)
{
    int i = blockIdx.x * blockDim.x + threadIdx.x;
    if (i >= n4) return;
    float4 v = ((const float4*)in)[i];
    ((uint2*)out)[i] = make_uint2(pack_h2(v.x, v.y), pack_h2(v.z, v.w));
}

// ---------------------------------------------------------------------------
// Bias gather (fp16 output)
// ---------------------------------------------------------------------------
__global__ void bias_gather_kernel(const float* __restrict__ table) {
    int idx = blockIdx.x * blockDim.x + threadIdx.x;
    if (idx >= NTOK * NTOK) return;
    int i = idx / NTOK, j = idx % NTOK;
    int ri = i / WIN, ci = i % WIN;
    int rj = j / WIN, cj = j % WIN;
    int t = (ri - rj + WIN - 1) * (2 * WIN - 1) + (ci - cj + WIN - 1);
#pragma unroll
    for (int h = 0; h < HEADS; h++)
        g_bias16[h * (NTOK * NTOK) + idx] = __float2half(table[t * HEADS + h]);
}

// ---------------------------------------------------------------------------
// fp16 mma.sync GEMM (R10 structure; epilogue bias loads hoisted).
// 128x256 CTA tile, 512 threads, K-tile 64, 3-stage cp.async ring.
// ---------------------------------------------------------------------------
#define KT    64
#define KSA   72
#define KSB2  264
#define A_SZ  (128 * KSA)
#define B_SZ2 (KT * KSB2)
#define BUFSZ (A_SZ + B_SZ2)
#define NBUF  3
#define GEMM_SMEM_BYTES (NBUF * BUFSZ * 2)

__device__ __forceinline__ void gemm_stage(
    uint32_t base, int bufo,
    const __half* A16, const __half* B16,
    int row0, int col0, int k0, int K, int N, int tid)
{
#pragma unroll
    for (int s = 0; s < 2; s++) {
        int id = tid + s * 512;
        int r = id >> 3, c = (id & 7) * 8;
        size_t g = (size_t)(row0 + r) * K + k0 + c;
        CP_A16(base + 2 * (bufo + r * KSA + c), A16 + g);
    }
#pragma unroll
    for (int s = 0; s < 4; s++) {
        int id = tid + s * 512;
        int k = id >> 5, n = (id & 31) * 8;
        size_t g = (size_t)(k0 + k) * N + col0 + n;
        CP_A16(base + 2 * (bufo + A_SZ + k * KSB2 + n), B16 + g);
    }
}

__global__ __launch_bounds__(512, 1) void gemm_f16_kernel(
    const __half* __restrict__ A16, const __half* __restrict__ B16,
    const float* __restrict__ bias,
    float* __restrict__ C, __half* __restrict__ C16,
    int M, int N, int K, int out_f16)
{
    extern __shared__ __half sm[];
    const uint32_t base = (uint32_t)__cvta_generic_to_shared(sm);

    const int tid  = threadIdx.x;
    const int warp = tid >> 5;
    const int lane = tid & 31;
    const int wm = warp & 1;
    const int wn = warp >> 1;
    const int row0 = blockIdx.y * 128;
    const int col0 = blockIdx.x * 256;

    const int aBase = (wm * 64 + (lane & 15)) * KSA + (lane >> 4) * 8;
    const int bBase = (((lane >> 3) & 1) * 8 + (lane & 7)) * KSB2
                    + wn * 32 + (lane >> 4) * 8;

    float acc[4][4][4];
#pragma unroll
    for (int i = 0; i < 4; i++)
#pragma unroll
        for (int j = 0; j < 4; j++)
#pragma unroll
            for (int r = 0; r < 4; r++) acc[i][j][r] = 0.0f;

    const int nkt = K / KT;
    gemm_stage(base, 0 * BUFSZ, A16, B16, row0, col0, 0,  K, N, tid); CP_COMMIT();
    gemm_stage(base, 1 * BUFSZ, A16, B16, row0, col0, KT, K, N, tid); CP_COMMIT();

    int buf = 0;
    for (int kt = 0; kt < nkt; kt++) {
        const int bufo = buf * BUFSZ;
        const int oA = bufo;
        const int oB = bufo + A_SZ;

        CP_WAIT1();
        __syncthreads();

        if (kt + 2 < nkt) {
            int nb = buf + 2; if (nb >= 3) nb -= 3;
            gemm_stage(base, nb * BUFSZ, A16, B16,
                       row0, col0, (kt + 2) * KT, K, N, tid);
        }
        CP_COMMIT();

#pragma unroll
        for (int kk = 0; kk < KT; kk += 16) {
            uint32_t bh[4][2];
#pragma unroll
            for (int p = 0; p < 2; p++) {
                uint32_t r0, r1, r2, r3;
                uint32_t addr = base + 2 * (oB + bBase + kk * KSB2 + p * 16);
                LDSM_X4_T(r0, r1, r2, r3, addr);
                bh[2*p][0] = r0; bh[2*p][1] = r1; bh[2*p+1][0] = r2; bh[2*p+1][1] = r3;
            }
#pragma unroll
            for (int mt = 0; mt < 4; mt++) {
                uint32_t a0, a1, a2, a3;
                uint32_t addr = base + 2 * (oA + aBase + mt * 16 * KSA + kk);
                LDSM_X4(a0, a1, a2, a3, addr);
#pragma unroll
                for (int nt = 0; nt < 4; nt++)
                    mma_fp16(acc[mt][nt][0], acc[mt][nt][1], acc[mt][nt][2], acc[mt][nt][3],
                             a0, a1, a2, a3, bh[nt][0], bh[nt][1]);
            }
        }
        if (++buf == 3) buf = 0;
    }

    // epilogue (bias loads hoisted out of the mt loop)
    float bb[4][2];
#pragma unroll
    for (int nt = 0; nt < 4; nt++) {
        const int c = col0 + wn * 32 + nt * 8 + (lane & 3) * 2;
        bb[nt][0] = __ldg(bias + c);
        bb[nt][1] = __ldg(bias + c + 1);
    }
#pragma unroll
    for (int mt = 0; mt < 4; mt++) {
        const int r0 = row0 + wm * 64 + mt * 16 + (lane >> 2);
#pragma unroll
        for (int nt = 0; nt < 4; nt++) {
            const int c = col0 + wn * 32 + nt * 8 + (lane & 3) * 2;
            float v0 = acc[mt][nt][0] + bb[nt][0], v1 = acc[mt][nt][1] + bb[nt][1];
            float v2 = acc[mt][nt][2] + bb[nt][0], v3 = acc[mt][nt][3] + bb[nt][1];
            if (out_f16) {
                *(uint32_t*)(C16 + (size_t)r0 * N + c)       = pack_h2(v0, v1);
                *(uint32_t*)(C16 + (size_t)(r0 + 8) * N + c) = pack_h2(v2, v3);
            } else {
                *(float2*)(C + (size_t)r0 * N + c)       = make_float2(v0, v1);
                *(float2*)(C + (size_t)(r0 + 8) * N + c) = make_float2(v2, v3);
            }
        }
    }
}

// ---------------------------------------------------------------------------
// fp16 window attention (R13 structure: 2 CTAs per (b,h), 224 threads =
// 7 warps x 16 rows; chunk0 = 14 ntiles, chunk1 = 12 ntiles, K/V pad 208).
// R14/R15: Q fragments hoisted out of chunk loop; bias loads fp16.
// ---------------------------------------------------------------------------
#define QS      72
#define QROWS   112
#define NPAD    208
#define QSZ2    (QROWS * QS)
#define KSZ     (NPAD * QS)
#define ATT_SMEM_BYTES ((QSZ2 + 2 * KSZ) * 2)   // 76032 B

__global__ __launch_bounds__(224, 2) void attn_mma_kernel() {
    extern __shared__ __half smA[];
    const uint32_t base = (uint32_t)__cvta_generic_to_shared(smA);
    const uint32_t uQ = base;
    const uint32_t uK = base + 2 * QSZ2;
    const uint32_t uV = base + 2 * (QSZ2 + KSZ);

    const int h = blockIdx.x;
    const int b = blockIdx.y;
    const int qrow0 = blockIdx.z * QROWS;     // 0 or 112
    const int tid = threadIdx.x;
    const size_t rowbase = (size_t)b * NTOK;

    // zero pads: Q local rows with global row >= 196; K/V rows 196..207
    {
        uint2 z = make_uint2(0u, 0u);
        if (qrow0 + QROWS > NTOK) {
            for (int t = tid; t < (qrow0 + QROWS - NTOK) * 16; t += 224) {
                int r = (NTOK - qrow0) + (t >> 4), c = (t & 15) * 4;
                *(uint2*)&smA[r * QS + c] = z;
            }
        }
        for (int t = tid; t < 12 * 16; t += 224) {
            int r = 196 + (t >> 4), c = (t & 15) * 4;
            *(uint2*)&smA[QSZ2 + r * QS + c] = z;
            *(uint2*)&smA[QSZ2 + KSZ + r * QS + c] = z;
        }
    }

    // cp.async stage Q half + full K/V
    {
        const size_t gbase = rowbase * (3 * DIM) + h * HDIM;
        const int qvalid = min(QROWS, NTOK - qrow0);   // 112 or 84
        for (int t = tid; t < qvalid * 8; t += 224) {
            int r = t >> 3, c = (t & 7) * 8;
            size_t g = gbase + (size_t)(qrow0 + r) * (3 * DIM) + c;
            CP_A16(uQ + 2 * (r * QS + c), g_qkv16 + g);
        }
        for (int t = tid; t < NTOK * 8; t += 224) {
            int r = t >> 3, c = (t & 7) * 8;
            size_t g = gbase + (size_t)r * (3 * DIM) + c;
            uint32_t d = 2 * (r * QS + c);
            CP_A16(uK + d, g_qkv16 + g + DIM);
            CP_A16(uV + d, g_qkv16 + g + 2 * DIM);
        }
        CP_COMMIT();
        CP_WAIT0();
    }
    __syncthreads();

    const int warp = tid >> 5;
    const int lane = tid & 31;
    const int rows0 = warp * 16;              // local

    float o[8][4];
#pragma unroll
    for (int i = 0; i < 8; i++)
#pragma unroll
        for (int r = 0; r < 4; r++) o[i][r] = 0.0f;
    float sum0 = 0.0f, sum1 = 0.0f;

    const int rA = qrow0 + rows0 + (lane >> 2);   // global query row
    const int rB = rA + 8;
    const int rAc = min(rA, NTOK - 1);
    const int rBc = min(rB, NTOK - 1);
    const __half* biasH = g_bias16 + h * (NTOK * NTOK);

    const int qBase = (rows0 + (lane & 15)) * QS + (lane >> 4) * 8;
    const int kBaseRow = (lane & 15);
    const int vBaseRow = ((lane >> 3) & 1) * 8 + (lane & 7);

    // Q fragments — chunk-invariant, loaded ONCE
    uint32_t qh[4][4];
#pragma unroll
    for (int ks = 0; ks < 4; ks++) {
        uint32_t addr = uQ + 2 * (qBase + ks * 16);
        LDSM_X4(qh[ks][0], qh[ks][1], qh[ks][2], qh[ks][3], addr);
    }

#pragma unroll
    for (int c = 0; c < 2; c++) {
        const int j0 = c * 112;
        const int NT = c ? 12 : 14;      // ntiles this chunk (compile-time)
        const int NP = NT / 2;

        float s[14][4];
#pragma unroll
        for (int nt = 0; nt < NT; nt++)
#pragma unroll
            for (int r = 0; r < 4; r++) s[nt][r] = 0.0f;

#pragma unroll
        for (int ntp = 0; ntp < NP; ntp++) {
#pragma unroll
            for (int ks = 0; ks < 4; ks++) {
                uint32_t kh0, kh1, kh2, kh3;
                uint32_t addr = uK + 2 * ((j0 + ntp * 16 + kBaseRow) * QS
                                          + (lane >> 4) * 8 + ks * 16);
                LDSM_X4(kh0, kh1, kh2, kh3, addr);
                float* s0 = s[2 * ntp];
                float* s1 = s[2 * ntp + 1];
                mma_fp16(s0[0], s0[1], s0[2], s0[3],
                         qh[ks][0], qh[ks][1], qh[ks][2], qh[ks][3], kh0, kh2);
                mma_fp16(s1[0], s1[1], s1[2], s1[3],
                         qh[ks][0], qh[ks][1], qh[ks][2], qh[ks][3], kh1, kh3);
            }
        }

        // bias (fp16 loads) + mask + exp
        uint32_t pa[14], pb_[14];
#pragma unroll
        for (int nt = 0; nt < NT; nt++) {
            int col = j0 + nt * 8 + (lane & 3) * 2;
            int colc = min(col, NTOK - 2);
            float2 bA = unpack_h2(*(const uint32_t*)(biasH + rAc * NTOK + colc));
            float2 bB = unpack_h2(*(const uint32_t*)(biasH + rBc * NTOK + colc));
            float v0 = fmaf(s[nt][0], SCALE_F, bA.x);
            float v1 = fmaf(s[nt][1], SCALE_F, bA.y);
            float v2 = fmaf(s[nt][2], SCALE_F, bB.x);
            float v3 = fmaf(s[nt][3], SCALE_F, bB.y);
            if (col     >= NTOK) { v0 = -1e30f; v2 = -1e30f; }
            if (col + 1 >= NTOK) { v1 = -1e30f; v3 = -1e30f; }
            float p0 = fast_exp(v0);
            float p1 = fast_exp(v1);
            float p2 = fast_exp(v2);
            float p3 = fast_exp(v3);
            sum0 += p0 + p1;
            sum1 += p2 + p3;
            pa[nt]  = pack_h2(p0, p1);
            pb_[nt] = pack_h2(p2, p3);
        }

#pragma unroll
        for (int q = 0; q < NP; q++) {
            uint32_t a0 = pa[2*q], a1 = pb_[2*q], a2 = pa[2*q+1], a3 = pb_[2*q+1];
#pragma unroll
            for (int vn = 0; vn < 4; vn++) {
                uint32_t vh0, vh1, vh2, vh3;
                uint32_t addr = uV + 2 * ((j0 + q * 16 + vBaseRow) * QS
                                          + vn * 16 + (lane >> 4) * 8);
                LDSM_X4_T(vh0, vh1, vh2, vh3, addr);
                float* o0 = o[2 * vn];
                float* o1 = o[2 * vn + 1];
                mma_fp16(o0[0], o0[1], o0[2], o0[3], a0, a1, a2, a3, vh0, vh1);
                mma_fp16(o1[0], o1[1], o1[2], o1[3], a0, a1, a2, a3, vh2, vh3);
            }
        }
    }

    sum0 += __shfl_xor_sync(0xffffffff, sum0, 1);
    sum0 += __shfl_xor_sync(0xffffffff, sum0, 2);
    sum1 += __shfl_xor_sync(0xffffffff, sum1, 1);
    sum1 += __shfl_xor_sync(0xffffffff, sum1, 2);
    float r0s = 1.0f / sum0;
    float r1s = 1.0f / sum1;

    const size_t obase = rowbase * DIM + h * HDIM;
#pragma unroll
    for (int nt = 0; nt < 8; nt++) {
        int col = nt * 8 + (lane & 3) * 2;
        if (rA < NTOK)
            *(uint32_t*)(g_at16 + obase + (size_t)rA * DIM + col) =
                pack_h2(o[nt][0] * r0s, o[nt][1] * r0s);
        if (rB < NTOK)
            *(uint32_t*)(g_at16 + obase + (size_t)rB * DIM + col) =
                pack_h2(o[nt][2] * r1s, o[nt][3] * r1s);
    }
}

// ---------------------------------------------------------------------------
// Launch
// ---------------------------------------------------------------------------
extern "C" void kernel_launch(void* const* d_in, const int* in_sizes, int n_in,
                              void* d_out, int out_size)
{
    const float* x          = (const float*)d_in[0];
    const float* w_qkv      = (const float*)d_in[1];
    const float* b_qkv      = (const float*)d_in[2];
    const float* w_proj     = (const float*)d_in[3];
    const float* b_proj     = (const float*)d_in[4];
    const float* bias_table = (const float*)d_in[5];
    float* out              = (float*)d_out;

    __half *x16, *wq16, *wp16, *qkv16, *at16;
    cudaGetSymbolAddress((void**)&x16,   g_x16);
    cudaGetSymbolAddress((void**)&wq16,  g_wq16);
    cudaGetSymbolAddress((void**)&wp16,  g_wp16);
    cudaGetSymbolAddress((void**)&qkv16, g_qkv16);
    cudaGetSymbolAddress((void**)&at16,  g_at16);

    cudaFuncSetAttribute(gemm_f16_kernel,
                         cudaFuncAttributeMaxDynamicSharedMemorySize,
                         GEMM_SMEM_BYTES);
    cudaFuncSetAttribute(attn_mma_kernel,
                         cudaFuncAttributeMaxDynamicSharedMemorySize,
                         ATT_SMEM_BYTES);

    bias_gather_kernel<<<(NTOK * NTOK + 255) / 256, 256>>>(bias_table);

    {   // fp32 -> fp16 conversions
        int n4 = MROWS * DIM / 4;
        convert_f16_kernel<<<(n4 + 255) / 256, 256>>>(x, x16, n4);
        n4 = DIM * 3 * DIM / 4;
        convert_f16_kernel<<<(n4 + 255) / 256, 256>>>(w_qkv, wq16, n4);
        n4 = DIM * DIM / 4;
        convert_f16_kernel<<<(n4 + 255) / 256, 256>>>(w_proj, wp16, n4);
    }

    {   // QKV GEMM -> fp16 output
        dim3 grid(3 * DIM / 256, MROWS / 128);
        gemm_f16_kernel<<<grid, 512, GEMM_SMEM_BYTES>>>(
            x16, wq16, b_qkv, nullptr, qkv16, MROWS, 3 * DIM, DIM, 1);
    }

    {   // window attention: 2 CTAs per (h,b), each 112 query rows
        dim3 grid(HEADS, BATCH, 2);
        attn_mma_kernel<<<grid, 224, ATT_SMEM_BYTES>>>();
    }

    {   // output projection -> fp32
        dim3 grid(DIM / 256, MROWS / 128);
        gemm_f16_kernel<<<grid, 512, GEMM_SMEM_BYTES>>>(
            at16, wp16, b_proj, out, nullptr, MROWS, DIM, DIM, 0);
    }
}